// round 16
// baseline (speedup 1.0000x reference)
#include <cuda_runtime.h>
#include <math.h>

// Problem shape (fixed): B=256, T=1024, H=128, FUTURE=32.
#define BB    256
#define HH    128
#define KK1   129
#define KK2   257
#define KK3   385
#define NTHR  256          // 8 warps: 4 row-pair warps x 2 k-sets
// 256 CTAs: 0..127 alpha (cell1+cell2, 8 rows), 128..255 beta (cell3+head)

// ---------------- device-global exchange state (allocation-free) -------------
__device__ __align__(16) float g_h1[2][HH * BB];
__device__ __align__(16) float g_h2[2][HH * BB];
__device__ __align__(16) float g_h3[2][HH * BB];
__device__ __align__(16) float g_ox[BB];
__device__ int g_flags[392 * 32];
// lines 0..127    : alpha(hg*8+bg)  -> 2t+1 after h1(t), 2t+2 after h2(t)
// lines 128..255  : beta intra      -> t+1 after h3(t) stored
// lines 256..383  : beta consumed   -> t+1 after staging h1(t),h2(t)
// lines 384..391  : o ready per bg  -> t+1 after o(t) in g_ox

__global__ void lstm_bar_init() {
    for (int i = threadIdx.x; i < 392 * 32; i += blockDim.x) g_flags[i] = 0;
}

// ---------------- flags ------------------------------------------------------
__device__ __forceinline__ void flag_set(int line, int val, int tid) {
    if (tid == 0) {
        __threadfence();
        asm volatile("st.relaxed.gpu.s32 [%0], %1;"
                     :: "l"(g_flags + line * 32), "r"(val) : "memory");
    }
}
__device__ __forceinline__ void flag_wait16(int base, int bg, int target, int tid) {
    if (tid < 16) {
        int v;
        const int *fp = g_flags + (base + tid * 8 + bg) * 32;
        do {
            asm volatile("ld.relaxed.gpu.s32 %0, [%1];" : "=r"(v) : "l"(fp) : "memory");
        } while (v < target);
    }
    __threadfence();
    __syncthreads();
}
__device__ __forceinline__ void flag_wait1(int line, int target, int tid) {
    if (tid == 0) {
        int v;
        const int *fp = g_flags + line * 32;
        do {
            asm volatile("ld.relaxed.gpu.s32 %0, [%1];" : "=r"(v) : "l"(fp) : "memory");
        } while (v < target);
    }
    __threadfence();
    __syncthreads();
}

// ---------------- activations (HW tanh) --------------------------------------
__device__ __forceinline__ float tanha(float x) {
    float r; asm("tanh.approx.f32 %0, %1;" : "=f"(r) : "f"(x)); return r;
}
__device__ __forceinline__ float sigf(float v) {
    return fmaf(0.5f, tanha(0.5f * v), 0.5f);
}
__device__ __forceinline__ float lstm_out(float4 a, float &c) {
    float ig = sigf(a.x), fg = sigf(a.y);
    float gg = tanha(a.z), og = sigf(a.w);
    c = fg * c + ig * gg;
    return og * tanha(c);
}

// ---------------- gate accumulation: 2 rows x 4 gates per thread -------------
// ws: [k][rp(4)][rr(2)][gate(4)] floats = float4[k][8]
template <int K0, int K1>
__device__ __forceinline__ void accum2(const float4 *__restrict__ wsq,
                                       float4 &a0, float4 &a1,
                                       const float *__restrict__ in_s,
                                       int lane, int rp) {
    const float4 *wp = wsq + rp * 2;
    const float  *ip = in_s + lane;
#pragma unroll 4
    for (int k = K0; k < K1; k++) {
        float4 w0 = wp[k * 8];
        float4 w1 = wp[k * 8 + 1];
        float  v  = ip[k * 32];
        a0.x = fmaf(w0.x, v, a0.x); a0.y = fmaf(w0.y, v, a0.y);
        a0.z = fmaf(w0.z, v, a0.z); a0.w = fmaf(w0.w, v, a0.w);
        a1.x = fmaf(w1.x, v, a1.x); a1.y = fmaf(w1.y, v, a1.y);
        a1.z = fmaf(w1.z, v, a1.z); a1.w = fmaf(w1.w, v, a1.w);
    }
}

// combine 2 k-set partials: set1 (tid>=128) publishes, set0 sums.
__device__ __forceinline__ void combine2(float4 &a0, float4 &a1,
                                         float4 *psum, int tid, int set) {
    if (set == 1) {
        psum[(tid - 128) * 2]     = a0;
        psum[(tid - 128) * 2 + 1] = a1;
    }
    __syncthreads();
    if (set == 0) {
        float4 b0 = psum[tid * 2], b1 = psum[tid * 2 + 1];
        a0.x += b0.x; a0.y += b0.y; a0.z += b0.z; a0.w += b0.w;
        a1.x += b1.x; a1.y += b1.y; a1.z += b1.z; a1.w += b1.w;
    }
}

// stage one h vector (32 cols, 128 rows) L2 -> smem slot, 256 threads
__device__ __forceinline__ void stage_h(const float *__restrict__ src,
                                        float *__restrict__ dst, int tid) {
    const float4 *s4 = (const float4 *)src;
    float4 *d4 = (float4 *)dst;
#pragma unroll
    for (int i = 0; i < 4; i++) {
        int idx = tid + i * NTHR;          // 0..1023
        int row = idx >> 3, q = idx & 7;
        d4[row * 8 + q] = __ldcg(s4 + row * 64 + q);
    }
}

// ---------------- smem sizing (floats) ---------------------------------------
#define SMA_F (129*32 + 257*32 + 64 + 257*32 + 1024 + 32)
#define SMB_F (385*32 + 32 + 392 + 385*32 + 256 + 32 + 1024 + 32)
#define SMEM_F (SMB_F > SMA_F ? SMB_F : SMA_F)
#define SMEM_BYTES (SMEM_F * 4)

__global__ void __launch_bounds__(NTHR, 2)
lstm_pipe_kernel(const float *__restrict__ x,
                 const float *__restrict__ Wi1, const float *__restrict__ Wh1,
                 const float *__restrict__ bi1, const float *__restrict__ bh1,
                 const float *__restrict__ Wi2, const float *__restrict__ Wh2,
                 const float *__restrict__ bi2, const float *__restrict__ bh2,
                 const float *__restrict__ Wi3, const float *__restrict__ Wh3,
                 const float *__restrict__ bi3, const float *__restrict__ bh3,
                 const float *__restrict__ Wl,  const float *__restrict__ bl,
                 float *__restrict__ out, int T, int NT) {
    extern __shared__ float sm[];
    const int tid  = threadIdx.x;
    const int lane = tid & 31;
    const int wid  = tid >> 5;          // 0..7
    const int rp   = wid & 3;           // row-pair: rows 2rp, 2rp+1 (of 8)
    const int set  = wid >> 2;          // k-split set: 0,1
    const float4 zero4 = make_float4(0.f, 0.f, 0.f, 0.f);

    if (blockIdx.x < 128) {
        // =================== alpha : cell1 + cell2 (verbatim R11) ============
        const int hg = blockIdx.x >> 3, bg = blockIdx.x & 7;
        const int line = hg * 8 + bg;
        const int bcol = bg * 32 + lane;

        float *ws1f  = sm;
        float *ws2f  = ws1f + 129 * 32;
        float *biasf = ws2f + 257 * 32;
        float *big   = biasf + 64;
        float4 *psum = (float4 *)(big + 257 * 32);
        const float4 *ws1 = (const float4 *)ws1f;
        const float4 *ws2 = (const float4 *)ws2f;
        const float4 *bias4 = (const float4 *)biasf;

        for (int idx = tid; idx < 129 * 32; idx += NTHR) {
            int k = idx >> 5, t5 = idx & 31;
            int rpp = t5 >> 3, rr = (t5 >> 2) & 1, g = t5 & 3;
            int r = g * HH + hg * 8 + rpp * 2 + rr;
            ws1f[idx] = (k == 0) ? Wi1[r] : Wh1[r * HH + (k - 1)];
        }
        for (int idx = tid; idx < 257 * 32; idx += NTHR) {
            int k = idx >> 5, t5 = idx & 31;
            int rpp = t5 >> 3, rr = (t5 >> 2) & 1, g = t5 & 3;
            int r = g * HH + hg * 8 + rpp * 2 + rr;
            ws2f[idx] = (k < KK1) ? Wi2[r * KK1 + k] : Wh2[r * HH + (k - KK1)];
        }
        if (tid < 64) {
            int cell = tid >> 5, t5 = tid & 31;
            int rpp = t5 >> 3, rr = (t5 >> 2) & 1, g = t5 & 3;
            int r = g * HH + hg * 8 + rpp * 2 + rr;
            biasf[tid] = cell ? (bi2[r] + bh2[r]) : (bi1[r] + bh1[r]);
        }
        for (int idx = tid; idx < 257 * 32; idx += NTHR) big[idx] = 0.0f;
        __syncthreads();

        float c1a = 0.f, c1b = 0.f, c2a = 0.f, c2b = 0.f;
        const int gr0 = (hg * 8 + rp * 2) * BB + bcol;
        float xr = 0.f;
        if (tid < 32) xr = __ldg(&x[(bg * 32 + tid) * T]);

        for (int t = 0; t < NT; t++) {
            flag_wait16(256, bg, t - 1, tid);          // beta consumed (t-2)
            if (t >= T) {
                flag_wait1(384 + bg, t, tid);
                if (tid < 32) big[tid] = __ldcg(&g_ox[bg * 32 + tid]);
            } else {
                if (tid < 32) big[tid] = xr;
            }
            __syncthreads();

            // ---- cell 1 ------------------------------------------------------
            float4 a0, a1;
            if (set == 0) {
                a0 = bias4[rp * 2]; a1 = bias4[rp * 2 + 1];
                accum2<0, 65>(ws1, a0, a1, big, lane, rp);
            } else {
                a0 = zero4; a1 = zero4;
                accum2<65, 129>(ws1, a0, a1, big, lane, rp);
            }
            combine2(a0, a1, psum, tid, set);
            if (set == 0) {
                g_h1[t & 1][gr0]      = lstm_out(a0, c1a);
                g_h1[t & 1][gr0 + BB] = lstm_out(a1, c1b);
            }
            __syncthreads();
            flag_set(line, 2 * t + 1, tid);

            if (tid < 32 && t + 1 < T) xr = __ldg(&x[(bg * 32 + tid) * T + t + 1]);

            flag_wait16(0, bg, 2 * t, tid);            // nearly free
            if (t > 0) stage_h(&g_h2[(t - 1) & 1][bg * 32], big + 129 * 32, tid);
            __syncthreads();

            // ---- cell2 partial: x (k=0) + h2_prev (129..257) ----------------
            float4 b0, b1;
            if (set == 0) {
                b0 = bias4[8 + rp * 2]; b1 = bias4[8 + rp * 2 + 1];
                accum2<0, 1>(ws2, b0, b1, big, lane, rp);
                accum2<129, 193>(ws2, b0, b1, big, lane, rp);
            } else {
                b0 = zero4; b1 = zero4;
                accum2<193, 257>(ws2, b0, b1, big, lane, rp);
            }

            flag_wait16(0, bg, 2 * t + 1, tid);        // h1(t) from same-bg peers
            stage_h(&g_h1[t & 1][bg * 32], big + 32, tid);
            __syncthreads();

            // ---- cell 2 finish over h1_new ----------------------------------
            if (set == 0) accum2<1, 65>(ws2, b0, b1, big, lane, rp);
            else          accum2<65, 129>(ws2, b0, b1, big, lane, rp);
            combine2(b0, b1, psum, tid, set);
            if (set == 0) {
                g_h2[t & 1][gr0]      = lstm_out(b0, c2a);
                g_h2[t & 1][gr0 + BB] = lstm_out(b1, c2b);
            }
            __syncthreads();
            flag_set(line, 2 * t + 2, tid);
        }
    } else {
        // =================== beta : cell3 + head (SPLIT WAITS) ===============
        const int bidx = blockIdx.x - 128;
        const int hg = bidx >> 3, bg = bidx & 7;
        const int bcol = bg * 32 + lane;
        const int sub = wid;

        float *ws3f  = sm;
        float *biasf = ws3f + 385 * 32;
        float *wl    = biasf + 32;
        float *big   = wl + 392;
        float *po_s  = big + 385 * 32;
        float *ox    = po_s + 256;
        float4 *psum = (float4 *)(ox + 32);
        const float4 *ws3 = (const float4 *)ws3f;
        const float4 *bias4 = (const float4 *)biasf;

        for (int idx = tid; idx < 385 * 32; idx += NTHR) {
            int k = idx >> 5, t5 = idx & 31;
            int rpp = t5 >> 3, rr = (t5 >> 2) & 1, g = t5 & 3;
            int r = g * HH + hg * 8 + rpp * 2 + rr;
            ws3f[idx] = (k < 257) ? Wi3[r * 257 + k] : Wh3[r * HH + (k - 257)];
        }
        if (tid < 32) {
            int t5 = tid;
            int rpp = t5 >> 3, rr = (t5 >> 2) & 1, g = t5 & 3;
            int r = g * HH + hg * 8 + rpp * 2 + rr;
            biasf[tid] = bi3[r] + bh3[r];
        }
        for (int idx = tid; idx < 385; idx += NTHR) wl[idx] = Wl[idx];
        if (tid == 0) wl[385] = bl[0];
        if (tid < 32) ox[tid] = 0.0f;
        for (int idx = tid; idx < 385 * 32; idx += NTHR) big[idx] = 0.0f;
        __syncthreads();

        float c3a = 0.f, c3b = 0.f;
        const int gr0 = (hg * 8 + rp * 2) * BB + bcol;
        float xr = 0.f;
        if (tid < 32) xr = __ldg(&x[(bg * 32 + tid) * T]);

        for (int t = 0; t < NT; t++) {
            if (tid < 32) big[tid] = (t < T) ? xr : ox[tid];
            __syncthreads();

            // ---- cell3 partial: x (k=0) + h3_prev (257..385, persistent) ----
            float4 d0, d1;
            if (set == 0) {
                d0 = bias4[rp * 2]; d1 = bias4[rp * 2 + 1];
                accum2<0, 1>(ws3, d0, d1, big, lane, rp);
                accum2<257, 321>(ws3, d0, d1, big, lane, rp);
            } else {
                d0 = zero4; d1 = zero4;
                accum2<321, 385>(ws3, d0, d1, big, lane, rp);
            }

            // ---- SPLIT 1: h1(t) ready at 2t+1 (one cell earlier than 2t+2) --
            flag_wait16(0, bg, 2 * t + 1, tid);
            stage_h(&g_h1[t & 1][bg * 32], big + 32, tid);
            __syncthreads();

            // mid-range over h1 (overlaps alpha's cell2)
            if (set == 0) accum2<1, 65>(ws3, d0, d1, big, lane, rp);
            else          accum2<65, 129>(ws3, d0, d1, big, lane, rp);

            // ---- SPLIT 2: h2(t) ready at 2t+2 -------------------------------
            flag_wait16(0, bg, 2 * t + 2, tid);
            stage_h(&g_h2[t & 1][bg * 32], big + 129 * 32, tid);
            __syncthreads();
            flag_set(256 + hg * 8 + bg, t + 1, tid);   // consumed h1+h2

            if (tid < 32 && t + 1 < T) xr = __ldg(&x[(bg * 32 + tid) * T + t + 1]);

            // ---- cell 3 finish over h2 --------------------------------------
            if (set == 0) accum2<129, 193>(ws3, d0, d1, big, lane, rp);
            else          accum2<193, 257>(ws3, d0, d1, big, lane, rp);
            combine2(d0, d1, psum, tid, set);
            if (set == 0) {
                g_h3[t & 1][gr0]      = lstm_out(d0, c3a);
                g_h3[t & 1][gr0 + BB] = lstm_out(d1, c3b);
            }
            __syncthreads();
            flag_set(128 + hg * 8 + bg, t + 1, tid);   // intra-beta arrive

            // head partial over x,h1,h2 while peers store h3
            float hp = 0.0f;
            for (int k = sub; k < 257; k += 8)
                hp = fmaf(wl[k], big[k * 32 + lane], hp);

            flag_wait16(128, bg, t + 1, tid);
            stage_h(&g_h3[t & 1][bg * 32], big + 257 * 32, tid);  // persists to t+1
            __syncthreads();

            for (int k = 257 + sub; k < 385; k += 8)
                hp = fmaf(wl[k], big[k * 32 + lane], hp);
            po_s[sub * 32 + lane] = hp;
            __syncthreads();
            if (tid < 32) {
                float o = wl[385];
#pragma unroll
                for (int s = 0; s < 8; s++) o += po_s[s * 32 + tid];
                ox[tid] = o;
                if (hg == 0) {
                    out[(bg * 32 + tid) * NT + t] = o;
                    g_ox[bg * 32 + tid] = o;
                }
            }
            __syncthreads();
            if (hg == 0) flag_set(384 + bg, t + 1, tid);
        }
    }
}

extern "C" void kernel_launch(void* const* d_in, const int* in_sizes, int n_in,
                              void* d_out, int out_size) {
    const float *x   = (const float *)d_in[0];
    const float *Wi1 = (const float *)d_in[1];
    const float *Wh1 = (const float *)d_in[2];
    const float *bi1 = (const float *)d_in[3];
    const float *bh1 = (const float *)d_in[4];
    const float *Wi2 = (const float *)d_in[5];
    const float *Wh2 = (const float *)d_in[6];
    const float *bi2 = (const float *)d_in[7];
    const float *bh2 = (const float *)d_in[8];
    const float *Wi3 = (const float *)d_in[9];
    const float *Wh3 = (const float *)d_in[10];
    const float *bi3 = (const float *)d_in[11];
    const float *bh3 = (const float *)d_in[12];
    const float *Wl  = (const float *)d_in[13];
    const float *bl  = (const float *)d_in[14];
    float *out = (float *)d_out;

    int T  = in_sizes[0] / BB;   // 1024
    int NT = out_size / BB;      // 1056

    cudaFuncSetAttribute(lstm_pipe_kernel,
                         cudaFuncAttributeMaxDynamicSharedMemorySize, SMEM_BYTES);

    lstm_bar_init<<<1, 256>>>();
    lstm_pipe_kernel<<<256, NTHR, SMEM_BYTES>>>(
        x, Wi1, Wh1, bi1, bh1, Wi2, Wh2, bi2, bh2,
        Wi3, Wh3, bi3, bh3, Wl, bl, out, T, NT);
}